// round 1
// baseline (speedup 1.0000x reference)
#include <cuda_runtime.h>
#include <math.h>

// Problem constants (fixed by reference setup_inputs)
#define N_BATCH 256
#define M_ROWS  8
#define T_LEN   16384
#define SPLITS  4
#define NPAIRS  36          // 8*9/2 lower-tri (symmetric Gram)
#define THREADS 256
#define T4_PER_SPLIT (T_LEN / 4 / SPLITS)   // 1024 float4 per split
#define ITERS (T4_PER_SPLIT / THREADS)      // 4

// Deterministic partial-sum scratch (no atomics, no allocation)
__device__ float g_partial[N_BATCH * SPLITS * NPAIRS];

__global__ void __launch_bounds__(THREADS)
gram_partial_kernel(const float* __restrict__ X) {
    const int cta   = blockIdx.x;
    const int n     = cta / SPLITS;
    const int split = cta % SPLITS;
    const int tid   = threadIdx.x;

    const float4* __restrict__ base =
        reinterpret_cast<const float4*>(X + (size_t)n * M_ROWS * T_LEN);
    const int t4_start = split * T4_PER_SPLIT + tid;

    float acc[NPAIRS];
#pragma unroll
    for (int i = 0; i < NPAIRS; i++) acc[i] = 0.f;

#pragma unroll
    for (int it = 0; it < ITERS; it++) {
        const int t4 = t4_start + it * THREADS;
        float4 v[M_ROWS];
#pragma unroll
        for (int m = 0; m < M_ROWS; m++)
            v[m] = base[m * (T_LEN / 4) + t4];

        int idx = 0;
#pragma unroll
        for (int m = 0; m < M_ROWS; m++) {
#pragma unroll
            for (int k = 0; k <= m; k++) {
                acc[idx] = fmaf(v[m].x, v[k].x, acc[idx]);
                acc[idx] = fmaf(v[m].y, v[k].y, acc[idx]);
                acc[idx] = fmaf(v[m].z, v[k].z, acc[idx]);
                acc[idx] = fmaf(v[m].w, v[k].w, acc[idx]);
                idx++;
            }
        }
    }

    // Intra-warp tree reduce for each of the 36 sums
#pragma unroll
    for (int i = 0; i < NPAIRS; i++) {
#pragma unroll
        for (int off = 16; off > 0; off >>= 1)
            acc[i] += __shfl_down_sync(0xffffffffu, acc[i], off);
    }

    __shared__ float sred[THREADS / 32][NPAIRS];
    const int warp = tid >> 5;
    const int lane = tid & 31;
    if (lane == 0) {
#pragma unroll
        for (int i = 0; i < NPAIRS; i++) sred[warp][i] = acc[i];
    }
    __syncthreads();

    if (tid < NPAIRS) {
        float s = 0.f;
#pragma unroll
        for (int w = 0; w < THREADS / 32; w++) s += sred[w][tid];
        g_partial[(n * SPLITS + split) * NPAIRS + tid] = s;
    }
}

__device__ __forceinline__ int cidx(int a, int b) {
    const int m = a > b ? a : b;
    const int k = a > b ? b : a;
    return m * (m + 1) / 2 + k;
}

__global__ void __launch_bounds__(N_BATCH)
finalize_kernel(float* __restrict__ out) {
    const int n = threadIdx.x;
    if (n >= N_BATCH) return;

    // C = Gram / T
    float C[NPAIRS];
#pragma unroll
    for (int i = 0; i < NPAIRS; i++) {
        float s = 0.f;
#pragma unroll
        for (int sp = 0; sp < SPLITS; sp++)
            s += g_partial[(n * SPLITS + sp) * NPAIRS + i];
        C[i] = s * (1.0f / (float)T_LEN);
    }

    // R[s1][s2] = mean over j of C[j+s1][j+s2]; upper triangle (row-major),
    // matching jnp.triu_indices(5) ordering.
    float tri[15];
    int p = 0;
#pragma unroll
    for (int s1 = 0; s1 < 5; s1++) {
#pragma unroll
        for (int s2 = s1; s2 < 5; s2++) {
            float r = 0.f;
#pragma unroll
            for (int j = 0; j < 4; j++)
                r += C[cidx(j + s1, j + s2)];
            tri[p++] = r * 0.25f;
        }
    }

    // feat = [tri (15), zeros (15)]; standardize over all 30 (population std)
    float mean = 0.f;
#pragma unroll
    for (int i = 0; i < 15; i++) mean += tri[i];
    mean *= (1.0f / 30.0f);

    float var = 0.f;
#pragma unroll
    for (int i = 0; i < 15; i++) {
        const float d = tri[i] - mean;
        var += d * d;
    }
    var += 15.0f * mean * mean;   // the 15 zero entries contribute (0-mean)^2
    var *= (1.0f / 30.0f);

    const float inv = 1.0f / (sqrtf(var) + 1e-8f);

    float* o = out + n * 30;
#pragma unroll
    for (int i = 0; i < 15; i++) o[i] = (tri[i] - mean) * inv;
    const float zval = (0.0f - mean) * inv;
#pragma unroll
    for (int i = 15; i < 30; i++) o[i] = zval;
}

extern "C" void kernel_launch(void* const* d_in, const int* in_sizes, int n_in,
                              void* d_out, int out_size) {
    const float* X = (const float*)d_in[0];
    float* out = (float*)d_out;

    gram_partial_kernel<<<N_BATCH * SPLITS, THREADS>>>(X);
    finalize_kernel<<<1, N_BATCH>>>(out);
}

// round 2
// speedup vs baseline: 1.4870x; 1.4870x over previous
#include <cuda_runtime.h>
#include <math.h>

// Problem constants (fixed by reference setup_inputs)
#define N_BATCH 256
#define M_ROWS  8
#define T_LEN   16384
#define NPAIRS  36          // 8*9/2 lower-tri (symmetric Gram)
#define THREADS 512
#define NWARPS  (THREADS / 32)
#define T4      (T_LEN / 4)              // 4096 float4 per row
#define ITERS   (T4 / THREADS)           // 8

__device__ __forceinline__ int cidx(int a, int b) {
    const int m = a > b ? a : b;
    const int k = a > b ? b : a;
    return m * (m + 1) / 2 + k;
}

__global__ void __launch_bounds__(THREADS)
ssf_fused_kernel(const float* __restrict__ X, float* __restrict__ out) {
    const int n   = blockIdx.x;
    const int tid = threadIdx.x;

    const float4* __restrict__ base =
        reinterpret_cast<const float4*>(X + (size_t)n * M_ROWS * T_LEN);

    float acc[NPAIRS];
#pragma unroll
    for (int i = 0; i < NPAIRS; i++) acc[i] = 0.f;

#pragma unroll
    for (int it = 0; it < ITERS; it++) {
        const int t4 = tid + it * THREADS;
        float4 v[M_ROWS];
#pragma unroll
        for (int m = 0; m < M_ROWS; m++)
            v[m] = base[m * T4 + t4];

        int idx = 0;
#pragma unroll
        for (int m = 0; m < M_ROWS; m++) {
#pragma unroll
            for (int k = 0; k <= m; k++) {
                acc[idx] = fmaf(v[m].x, v[k].x, acc[idx]);
                acc[idx] = fmaf(v[m].y, v[k].y, acc[idx]);
                acc[idx] = fmaf(v[m].z, v[k].z, acc[idx]);
                acc[idx] = fmaf(v[m].w, v[k].w, acc[idx]);
                idx++;
            }
        }
    }

    // Intra-warp tree reduce for each of the 36 sums
#pragma unroll
    for (int i = 0; i < NPAIRS; i++) {
#pragma unroll
        for (int off = 16; off > 0; off >>= 1)
            acc[i] += __shfl_down_sync(0xffffffffu, acc[i], off);
    }

    __shared__ float sred[NWARPS][NPAIRS];
    __shared__ float sC[NPAIRS];
    const int warp = tid >> 5;
    const int lane = tid & 31;
    if (lane == 0) {
#pragma unroll
        for (int i = 0; i < NPAIRS; i++) sred[warp][i] = acc[i];
    }
    __syncthreads();

    if (tid < NPAIRS) {
        float s = 0.f;
#pragma unroll
        for (int w = 0; w < NWARPS; w++) s += sred[w][tid];
        sC[tid] = s * (1.0f / (float)T_LEN);   // C = Gram / T
    }
    __syncthreads();

    if (tid == 0) {
        // R[s1][s2] = mean over j of C[j+s1][j+s2]; upper triangle in
        // jnp.triu_indices(5) (row-major) order.
        float tri[15];
        int p = 0;
#pragma unroll
        for (int s1 = 0; s1 < 5; s1++) {
#pragma unroll
            for (int s2 = s1; s2 < 5; s2++) {
                float r = 0.f;
#pragma unroll
                for (int j = 0; j < 4; j++)
                    r += sC[cidx(j + s1, j + s2)];
                tri[p++] = r * 0.25f;
            }
        }

        // feat = [tri (15), zeros (15)]; standardize over all 30 (pop. std)
        float mean = 0.f;
#pragma unroll
        for (int i = 0; i < 15; i++) mean += tri[i];
        mean *= (1.0f / 30.0f);

        float var = 0.f;
#pragma unroll
        for (int i = 0; i < 15; i++) {
            const float d = tri[i] - mean;
            var += d * d;
        }
        var += 15.0f * mean * mean;   // 15 zero entries each contribute mean^2
        var *= (1.0f / 30.0f);

        const float inv = 1.0f / (sqrtf(var) + 1e-8f);

        float* o = out + n * 30;
#pragma unroll
        for (int i = 0; i < 15; i++) o[i] = (tri[i] - mean) * inv;
        const float zval = -mean * inv;
#pragma unroll
        for (int i = 15; i < 30; i++) o[i] = zval;
    }
}

extern "C" void kernel_launch(void* const* d_in, const int* in_sizes, int n_in,
                              void* d_out, int out_size) {
    const float* X = (const float*)d_in[0];
    float* out = (float*)d_out;
    ssf_fused_kernel<<<N_BATCH, THREADS>>>(X, out);
}